// round 12
// baseline (speedup 1.0000x reference)
#include <cuda_runtime.h>
#include <math.h>

__device__ float  g_WxT[300 * 768];
__device__ float4 g_Wpack[65536];
__device__ float  g_W1T[65536];
__device__ float  g_W2T[65536];
__device__ float  g_iou[512 * 768];
__device__ float  g_mat[2][511 * 256];
__device__ float  g_c[2][511 * 256];
__device__ float  g_hA[2][511 * 256];
__device__ float  g_cA[2][511 * 256];
__device__ float  g_pbT[2][256 * 512];
__device__ float  g_colsum[2][256];
__device__ float  g_treePart[2][1024 * 1280];
__device__ int    g_cntL[64];

__constant__ int c_off[9] = {0, 256, 384, 448, 480, 496, 504, 508, 510};
__constant__ int c_ES[9]  = {0, 8, 16, 32, 64, 64, 64, 64, 64};

__device__ __forceinline__ float sigm(float x) { return 1.0f / (1.0f + expf(-x)); }
__device__ __forceinline__ float tfast(float x) {
    float y; asm("tanh.approx.f32 %0,%1;" : "=f"(y) : "f"(x)); return y;
}

__global__ void reset_kernel() { if (threadIdx.x < 64) g_cntL[threadIdx.x] = 0; }

__device__ __forceinline__ float blksum(float v, float* red, int tid) {
    for (int o = 16; o; o >>= 1) v += __shfl_xor_sync(~0u, v, o);
    if ((tid & 31) == 0) red[tid >> 5] = v;
    __syncthreads();
    if (tid == 0) { float s = 0; for (int i = 0; i < 8; i++) s += red[i]; red[8] = s; }
    __syncthreads();
    float r = red[8]; __syncthreads(); return r;
}

// ---------- prep ----------
__global__ void prep_kernel(const float* __restrict__ W_ioux, const float* __restrict__ W_iouh,
                            const float* __restrict__ W_fh,   const float* __restrict__ W_attnh) {
    const int N1 = 300 * 768, N2 = 65536, N3 = 65536, N4 = 65536;
    for (int i = blockIdx.x * 256 + threadIdx.x; i < N1 + N2 + N3 + N4; i += 512 * 256) {
        if (i < N1) {
            int t = i / 768, j = i - t * 768;
            g_WxT[i] = W_ioux[j * 300 + t];
        } else if (i < N1 + N2) {
            int e = i - N1; int t = e >> 8, j = e & 255;
            g_Wpack[e] = make_float4(W_iouh[j * 256 + t], W_iouh[(256 + j) * 256 + t],
                                     W_iouh[(512 + j) * 256 + t], W_fh[j * 256 + t]);
        } else if (i < N1 + N2 + N3) {
            int e = i - N1 - N2; int ee = e >> 8, d = e & 255;
            g_W1T[e] = W_attnh[d * 512 + ee];
        } else {
            int e = i - N1 - N2 - N3; int ee = e >> 8, d = e & 255;
            g_W2T[e] = W_attnh[d * 512 + 256 + ee];
        }
    }
}

// ---------- leaf GEMM + counter-fused gate (R8-proven) ----------
__global__ void leaf_kernel(const int* __restrict__ l_idx, const int* __restrict__ r_idx,
                            const float* __restrict__ emb,
                            const float* __restrict__ b_ioux, const float* __restrict__ b_iouh) {
    __shared__ float xs[2400];
    __shared__ int sidx[8];
    __shared__ int fin;
    int tid = threadIdx.x, bid = blockIdx.x;
    int rowgrp = bid & 63, part = bid >> 6;
    if (tid < 8) {
        int grow = rowgrp * 8 + tid;
        sidx[tid] = (grow >= 256) ? r_idx[grow - 256] : l_idx[grow];
    }
    __syncthreads();
    for (int e = tid; e < 8 * 300; e += 256) {
        int rr = e / 300, t = e - rr * 300;
        xs[e] = emb[(long)sidx[rr] * 300 + t];
    }
    __syncthreads();
    int col = part * 256 + tid;
    float bias = b_ioux[col] + b_iouh[col];
    float acc[8];
#pragma unroll
    for (int r = 0; r < 8; r++) acc[r] = bias;
#pragma unroll 6
    for (int t = 0; t < 300; t++) {
        float w = g_WxT[t * 768 + col];
#pragma unroll
        for (int r = 0; r < 8; r++) acc[r] = fmaf(w, xs[r * 300 + t], acc[r]);
    }
#pragma unroll
    for (int r = 0; r < 8; r++) g_iou[(rowgrp * 8 + r) * 768 + col] = acc[r];
    __threadfence();
    if (tid == 0) fin = (atomicAdd(&g_cntL[rowgrp], 1) == 2);
    __syncthreads();
    if (!fin) return;
#pragma unroll
    for (int r = 0; r < 8; r++) {
        int row = rowgrp * 8 + r; int side = row >> 8, leaf = row & 255;
        const float* base = &g_iou[row * 768];
        float iv = sigm(__ldcg(base + tid));
        float ov = sigm(__ldcg(base + 256 + tid));
        float uv = tanhf(__ldcg(base + 512 + tid));
        float c = iv * uv, h = ov * tanhf(c);
        g_c[side][leaf * 256 + tid] = c;
        g_mat[side][leaf * 256 + tid] = h;
    }
}

// ---------- split-K tree GEMM partials ----------
template <int RT>
__global__ void accum_kernel(int mode, int lev) {
    __shared__ float smf[512];
    int tid = threadIdx.x, gb = blockIdx.x, g = blockIdx.y;
    int ES = c_ES[lev];
    int tg = gb / ES, es_ = gb - tg * ES;
    int eNa = 256 / ES, e0 = es_ * eNa;
    int offp = c_off[lev - 1];
    const float* hsrc = mode ? g_hA[g] : g_mat[g];
    int cnt = RT * 2 * eNa;
    for (int t = tid; t < cnt; t += 256) {
        int r = t / (2 * eNa), rem = t - r * 2 * eNa;
        int cc = rem / eNa, e = rem - cc * eNa;
        smf[t] = hsrc[(offp + 2 * (tg * RT + r) + cc) * 256 + e0 + e];
    }
    __syncthreads();
    float a0[RT], a1[RT], a2[RT], a3[RT], a4[RT];
#pragma unroll
    for (int r = 0; r < RT; r++) { a0[r] = a1[r] = a2[r] = a3[r] = a4[r] = 0.f; }
#pragma unroll 4
    for (int ee = 0; ee < eNa; ee++) {
        float4 w = g_Wpack[(e0 + ee) * 256 + tid];
#pragma unroll
        for (int r = 0; r < RT; r++) {
            float h0 = smf[r * 2 * eNa + ee], h1 = smf[r * 2 * eNa + eNa + ee];
            float hv = h0 + h1;
            a0[r] = fmaf(w.x, hv, a0[r]); a1[r] = fmaf(w.y, hv, a1[r]);
            a2[r] = fmaf(w.z, hv, a2[r]);
            a3[r] = fmaf(w.w, h0, a3[r]); a4[r] = fmaf(w.w, h1, a4[r]);
        }
    }
#pragma unroll
    for (int r = 0; r < RT; r++) {
        float* b = &g_treePart[g][((tg * RT + r) * ES + es_) * 1280];
        b[tid] = a0[r]; b[256 + tid] = a1[r]; b[512 + tid] = a2[r];
        b[768 + tid] = a3[r]; b[1024 + tid] = a4[r];
    }
}

// vectorized partial reduce into smem buf[0..1279] (R8/R11-proven)
__device__ __forceinline__ void reduce_parts(float* buf, int tid, int g, int node, int ES) {
    float4 A0 = make_float4(0, 0, 0, 0), A1 = make_float4(0, 0, 0, 0);
#pragma unroll 4
    for (int s = 0; s < ES; s++) {
        const float4* t4 = (const float4*)&g_treePart[g][(node * ES + s) * 1280];
        float4 v = __ldcg(t4 + tid);
        A0.x += v.x; A0.y += v.y; A0.z += v.z; A0.w += v.w;
        if (tid < 64) {
            v = __ldcg(t4 + 256 + tid);
            A1.x += v.x; A1.y += v.y; A1.z += v.z; A1.w += v.w;
        }
    }
    float4* b4 = (float4*)buf;
    b4[tid] = A0;
    if (tid < 64) b4[256 + tid] = A1;
    __syncthreads();
}

// ---------- no-attn gate (block per node) ----------
__global__ void gate_kernel(int lev, const float* __restrict__ bi, const float* __restrict__ bf) {
    __shared__ float smf[1280];
    int tid = threadIdx.x, node = blockIdx.x, g = blockIdx.y;
    int offp = c_off[lev - 1], offc = c_off[lev];
    reduce_parts(smf, tid, g, node, c_ES[lev]);
    float iv = sigm(smf[tid] + bi[tid]);
    float ov = sigm(smf[256 + tid] + bi[256 + tid]);
    float uv = tanhf(smf[512 + tid] + bi[512 + tid]);
    float f0 = sigm(smf[768 + tid] + bf[tid]);
    float f1 = sigm(smf[1024 + tid] + bf[tid]);
    const float* csrc = &g_c[g][(offp + 2 * node) * 256];
    float c = iv * uv + f0 * csrc[tid] + f1 * csrc[256 + tid];
    float h = ov * tanhf(c);
    g_c[g][(offc + node) * 256 + tid] = c;
    g_mat[g][(offc + node) * 256 + tid] = h;
}

// ---------- proj -> pbT + colsum ----------
__global__ void proj_kernel(const float* __restrict__ ba) {
    __shared__ float smf[1024];
    int tid = threadIdx.x, gb = blockIdx.x, g = blockIdx.y;
    if (gb < 128) {
        int mb = gb * 4;
#pragma unroll
        for (int r = 0; r < 4; r++) {
            int m = min(mb + r, 510);
            smf[r * 256 + tid] = g_mat[g][m * 256 + tid];
        }
        __syncthreads();
        float b0 = ba[tid]; float a0 = b0, a1 = b0, a2 = b0, a3 = b0;
#pragma unroll 8
        for (int e = 0; e < 256; e++) {
            float w = g_W2T[e * 256 + tid];
            a0 = fmaf(w, smf[e], a0);       a1 = fmaf(w, smf[256 + e], a1);
            a2 = fmaf(w, smf[512 + e], a2); a3 = fmaf(w, smf[768 + e], a3);
        }
        *(float4*)&g_pbT[g][tid * 512 + mb] = make_float4(a0, a1, a2, a3);
    } else {
        int qc = gb - 128;
        int d = tid & 63, rs = tid >> 6, dim = qc * 64 + d;
        float a = 0;
        for (int m = rs; m < 511; m += 4) a += g_mat[g][m * 256 + dim];
        smf[rs * 64 + d] = a;
        __syncthreads();
        if (rs == 0) g_colsum[g][dim] = smf[d] + smf[64 + d] + smf[128 + d] + smf[192 + d];
    }
}

// ---------- attend body: h in hsm, wa loaded, sync done; writes g_hA[g][grow] ----------
__device__ void attend_body(int tid, float* smf, int g, int grow) {
    float* hsm = smf; float* wa = smf + 256; float* hpP = smf + 512;
    float* es = smf + 1536; float* red = smf + 2048;
    float4* sp = (float4*)(smf + 2064);
    // hp = W1 @ h: 4-way e-split, float4 over d (R8-proven pattern)
    int er = tid >> 6, dq = tid & 63;
    float4 a = make_float4(0, 0, 0, 0);
    const float4* W14 = (const float4*)g_W1T;
#pragma unroll 8
    for (int e2 = 0; e2 < 64; e2++) {
        int e = er * 64 + e2;
        float4 wv = W14[e * 64 + dq];
        float hv = hsm[e];
        a.x = fmaf(wv.x, hv, a.x); a.y = fmaf(wv.y, hv, a.y);
        a.z = fmaf(wv.z, hv, a.z); a.w = fmaf(wv.w, hv, a.w);
    }
    float* d0 = &hpP[er * 256 + 4 * dq];
    d0[0] = a.x; d0[1] = a.y; d0[2] = a.z; d0[3] = a.w;
    __syncthreads();
    float hpv = hpP[tid] + hpP[256 + tid] + hpP[512 + tid] + hpP[768 + tid];
    __syncthreads();
    hpP[tid] = hpv;
    __syncthreads();
    // scores (lane-per-key) + max-free softmax (R11-proven)
    float s0 = 0.f, s1 = 0.f;
    const float* pbb = g_pbT[g];
#pragma unroll 4
    for (int d = 0; d < 256; d++) {
        float wv = wa[d], hv = hpP[d];
        s0 = fmaf(wv, tfast(hv + pbb[d * 512 + tid]), s0);
        s1 = fmaf(wv, tfast(hv + pbb[d * 512 + 256 + tid]), s1);
    }
    es[tid] = __expf(s0);
    es[256 + tid] = (tid == 255) ? 0.f : __expf(s1);
    __syncthreads();
    float inv = 1.0f / blksum(es[tid] + es[256 + tid], red, tid);
    // combine
    int q = tid & 63, st2 = tid >> 6;
    const float4* m4 = (const float4*)g_mat[g];
    float4 ac = make_float4(0, 0, 0, 0);
#pragma unroll 8
    for (int m = st2; m < 511; m += 4) {
        float4 mv = m4[m * 64 + q]; float e = es[m];
        ac.x = fmaf(e, mv.x, ac.x); ac.y = fmaf(e, mv.y, ac.y);
        ac.z = fmaf(e, mv.z, ac.z); ac.w = fmaf(e, mv.w, ac.w);
    }
    sp[st2 * 64 + q] = ac;
    __syncthreads();
    if (st2 == 0) {
        float4 t = sp[q], b1 = sp[64 + q], b2 = sp[128 + q], b3 = sp[192 + q];
        t.x += b1.x + b2.x + b3.x; t.y += b1.y + b2.y + b3.y;
        t.z += b1.z + b2.z + b3.z; t.w += b1.w + b2.w + b3.w;
        const float* cs = g_colsum[g];
        float* o = &g_hA[g][grow * 256 + 4 * q];
        o[0] = cs[4 * q + 0] - t.x * inv + hsm[4 * q + 0];
        o[1] = cs[4 * q + 1] - t.y * inv + hsm[4 * q + 1];
        o[2] = cs[4 * q + 2] - t.z * inv + hsm[4 * q + 2];
        o[3] = cs[4 * q + 3] - t.w * inv + hsm[4 * q + 3];
    }
}

// ---------- leaf attend: block per row ----------
__global__ void attend_leaf_kernel(const float* __restrict__ Wa) {
    __shared__ __align__(16) float smf[3088];
    int tid = threadIdx.x, n = blockIdx.x, g = blockIdx.y;
    smf[tid] = g_mat[1 - g][n * 256 + tid];
    smf[256 + tid] = Wa[tid];
    __syncthreads();
    attend_body(tid, smf, g, n);
}

// ---------- fused gate+attend (attended levels 1..8): block per node ----------
__global__ void gate_attend_kernel(int lev, const float* __restrict__ bi,
                                   const float* __restrict__ bf, const float* __restrict__ Wa) {
    __shared__ __align__(16) float smf[4368];
    int tid = threadIdx.x, node = blockIdx.x, g = blockIdx.y;
    int offp = c_off[lev - 1], offc = c_off[lev];
    float* gbuf = smf + 3088;
    reduce_parts(gbuf, tid, g, node, c_ES[lev]);
    float iv = sigm(gbuf[tid] + bi[tid]);
    float ov = sigm(gbuf[256 + tid] + bi[256 + tid]);
    float uv = tanhf(gbuf[512 + tid] + bi[512 + tid]);
    float f0 = sigm(gbuf[768 + tid] + bf[tid]);
    float f1 = sigm(gbuf[1024 + tid] + bf[tid]);
    const float* csrc = (lev == 1) ? &g_c[1 - g][(2 * node) * 256]
                                   : &g_cA[g][(offp + 2 * node) * 256];
    float c = iv * uv + f0 * csrc[tid] + f1 * csrc[256 + tid];
    float h = ov * tanhf(c);
    g_cA[g][(offc + node) * 256 + tid] = c;
    smf[tid] = h;
    smf[256 + tid] = Wa[tid];
    __syncthreads();
    attend_body(tid, smf, g, offc + node);
}

// ---------- classifier ----------
__global__ void final_kernel(const float* __restrict__ W_wh, const float* __restrict__ b_wh,
                             const float* __restrict__ W_wp, const float* __restrict__ b_wp,
                             float* __restrict__ out) {
    __shared__ float v[512];
    __shared__ float hid[128];
    int tid = threadIdx.x;
    float lh = tanhf(g_mat[0][510 * 256 + tid] + g_hA[1][510 * 256 + tid]);
    float rh = tanhf(g_hA[0][510 * 256 + tid] + g_mat[1][510 * 256 + tid]);
    v[tid] = lh * rh;
    v[256 + tid] = fabsf(lh - rh);
    __syncthreads();
    if (tid < 128) {
        float a = b_wh[tid];
        const float4* W4 = (const float4*)&W_wh[tid * 512];
        const float4* v4 = (const float4*)v;
#pragma unroll 8
        for (int e = 0; e < 128; e++) {
            float4 w = W4[e], x = v4[e];
            a = fmaf(w.x, x.x, fmaf(w.y, x.y, fmaf(w.z, x.z, fmaf(w.w, x.w, a))));
        }
        hid[tid] = sigm(a);
    }
    __syncthreads();
    if (tid < 32) {
        float z[5];
#pragma unroll
        for (int c = 0; c < 5; c++) {
            float a = 0.f;
            for (int e = tid; e < 128; e += 32) a = fmaf(W_wp[c * 128 + e], hid[e], a);
#pragma unroll
            for (int o = 16; o; o >>= 1) a += __shfl_xor_sync(~0u, a, o);
            z[c] = a + b_wp[c];
        }
        if (tid == 0) {
            float mx = z[0];
#pragma unroll
            for (int c = 1; c < 5; c++) mx = fmaxf(mx, z[c]);
            float s = 0.f;
#pragma unroll
            for (int c = 0; c < 5; c++) s += expf(z[c] - mx);
            float ls = logf(s);
#pragma unroll
            for (int c = 0; c < 5; c++) out[c] = z[c] - mx - ls;
        }
    }
}

// ================= host =================
static void launch_accum(int mode, int lev) {
    static const int RTt[9] = {0, 8, 8, 8, 8, 8, 4, 2, 1};
    static const int ESt[9] = {0, 8, 16, 32, 64, 64, 64, 64, 64};
    int k = 256 >> lev;
    int rt = RTt[lev];
    int blocks = (k / rt) * ESt[lev];
    dim3 grid(blocks, 2);
    switch (rt) {
        case 8: accum_kernel<8><<<grid, 256>>>(mode, lev); break;
        case 4: accum_kernel<4><<<grid, 256>>>(mode, lev); break;
        case 2: accum_kernel<2><<<grid, 256>>>(mode, lev); break;
        default: accum_kernel<1><<<grid, 256>>>(mode, lev); break;
    }
}

extern "C" void kernel_launch(void* const* d_in, const int* in_sizes, int n_in,
                              void* d_out, int out_size) {
    const int*   l_idx   = (const int*)d_in[0];
    const int*   r_idx   = (const int*)d_in[1];
    const float* emb     = (const float*)d_in[2];
    const float* W_ioux  = (const float*)d_in[3];
    const float* b_ioux  = (const float*)d_in[4];
    const float* W_iouh  = (const float*)d_in[5];
    const float* b_iouh  = (const float*)d_in[6];
    const float* W_fh    = (const float*)d_in[9];
    const float* b_fh    = (const float*)d_in[10];
    const float* Wa      = (const float*)d_in[11];
    const float* W_attnh = (const float*)d_in[12];
    const float* b_attnh = (const float*)d_in[13];
    const float* W_wh    = (const float*)d_in[14];
    const float* b_wh    = (const float*)d_in[15];
    const float* W_wp    = (const float*)d_in[16];
    const float* b_wp    = (const float*)d_in[17];
    float* out = (float*)d_out;

    reset_kernel<<<1, 64>>>();
    prep_kernel<<<512, 256>>>(W_ioux, W_iouh, W_fh, W_attnh);
    leaf_kernel<<<192, 256>>>(l_idx, r_idx, emb, b_ioux, b_iouh);

    for (int lev = 1; lev <= 8; lev++) {
        launch_accum(0, lev);
        gate_kernel<<<dim3(256 >> lev, 2), 256>>>(lev, b_iouh, b_fh);
    }

    proj_kernel<<<dim3(132, 2), 256>>>(b_attnh);
    attend_leaf_kernel<<<dim3(256, 2), 256>>>(Wa);

    for (int lev = 1; lev <= 8; lev++) {
        launch_accum(1, lev);
        gate_attend_kernel<<<dim3(256 >> lev, 2), 256>>>(lev, b_iouh, b_fh, Wa);
    }

    final_kernel<<<1, 256>>>(W_wh, b_wh, W_wp, b_wp, out);
}

// round 13
// speedup vs baseline: 1.3115x; 1.3115x over previous
#include <cuda_runtime.h>
#include <math.h>

#define NBLK 296
#define GBLK 148

__device__ float  g_WxT[300 * 768];
__device__ float4 g_Wpack[65536];
__device__ float  g_W1T[65536];
__device__ float  g_W2T[65536];
__device__ float  g_iou[512 * 768];
__device__ float  g_mat[2][511 * 256];
__device__ float  g_c[2][511 * 256];
__device__ float  g_hA[2][511 * 256];
__device__ float  g_cA[2][511 * 256];
__device__ float  g_hPre[2][511 * 256];
__device__ float  g_pbT[2][256 * 512];
__device__ float  g_colsum[2][256];
__device__ float  g_hp[2][16 * 256];
__device__ float  g_treePart[2][1024 * 1280];
__device__ int    g_barG[8];
__device__ int    g_barL[2][48];
__device__ int    g_cnt0[2][8][64];

__constant__ int c_off[9] = {0, 256, 384, 448, 480, 496, 504, 508, 510};
// mode-1 (attended) accum tables — unchanged from 492 baseline
__constant__ int c_RT[9]  = {0, 8, 8, 8, 8, 8, 4, 2, 1};
__constant__ int c_ES[9]  = {0, 8, 16, 32, 32, 16, 16, 16, 16};
// mode-0 (no-attn) fused accum+gate tables
__constant__ int c_RT0[9] = {0, 4, 4, 4, 4, 2, 2, 2, 1};
__constant__ int c_ES0[9] = {0, 4, 8, 16, 16, 16, 16, 16, 16};

__device__ __forceinline__ float sigm(float x) { return 1.0f / (1.0f + expf(-x)); }
__device__ __forceinline__ float tfast(float x) {
    float y; asm("tanh.approx.f32 %0,%1;" : "=f"(y) : "f"(x)); return y;
}

// ---- barrier: proven form (single counter, volatile poll + nanosleep) ----
__device__ __forceinline__ void gbarG(int id) {
    __syncthreads();
    if (threadIdx.x == 0) {
        __threadfence();
        atomicAdd(&g_barG[id], 1);
        while (((volatile int*)g_barG)[id] < NBLK) __nanosleep(64);
        __threadfence();
    }
    __syncthreads();
}
__device__ __forceinline__ void gbarL(int g, int id) {
    __syncthreads();
    if (threadIdx.x == 0) {
        __threadfence();
        atomicAdd(&g_barL[g][id], 1);
        while (((volatile int*)g_barL[g])[id] < GBLK) __nanosleep(64);
        __threadfence();
    }
    __syncthreads();
}

__global__ void reset_kernel() {
    int t = threadIdx.x;
    if (t < 8) g_barG[t] = 0;
    if (t < 96) ((int*)g_barL)[t] = 0;
    for (int i = t; i < 2 * 8 * 64; i += 256) ((int*)g_cnt0)[i] = 0;
}

__device__ __forceinline__ float blksum(float v, float* red, int tid) {
    for (int o = 16; o; o >>= 1) v += __shfl_xor_sync(~0u, v, o);
    if ((tid & 31) == 0) red[tid >> 5] = v;
    __syncthreads();
    if (tid == 0) { float s = 0; for (int i = 0; i < 8; i++) s += red[i]; red[8] = s; }
    __syncthreads();
    float r = red[8]; __syncthreads(); return r;
}

// ---------- prep ----------
__device__ void st_prep(int bid, int tid,
                        const float* __restrict__ W_ioux, const float* __restrict__ W_iouh,
                        const float* __restrict__ W_fh,   const float* __restrict__ W_attnh) {
    const int N1 = 300 * 768, N2 = 65536, N3 = 65536, N4 = 65536;
    for (int i = bid * 256 + tid; i < N1 + N2 + N3 + N4; i += NBLK * 256) {
        if (i < N1) {
            int t = i / 768, j = i - t * 768;
            g_WxT[i] = W_ioux[j * 300 + t];
        } else if (i < N1 + N2) {
            int e = i - N1; int t = e >> 8, j = e & 255;
            g_Wpack[e] = make_float4(W_iouh[j * 256 + t], W_iouh[(256 + j) * 256 + t],
                                     W_iouh[(512 + j) * 256 + t], W_fh[j * 256 + t]);
        } else if (i < N1 + N2 + N3) {
            int e = i - N1 - N2; int ee = e >> 8, d = e & 255;
            g_W1T[e] = W_attnh[d * 512 + ee];
        } else {
            int e = i - N1 - N2 - N3; int ee = e >> 8, d = e & 255;
            g_W2T[e] = W_attnh[d * 512 + 256 + ee];
        }
    }
}

// ---------- leaf GEMM ----------
__device__ void st_leafgemm(int bid, int tid, float* smf,
                            const int* __restrict__ l_idx, const int* __restrict__ r_idx,
                            const float* __restrict__ emb,
                            const float* __restrict__ b_ioux, const float* __restrict__ b_iouh) {
    if (bid >= 192) return;
    float* xs = smf;
    int* sidx = (int*)(smf + 2400);
    int rowgrp = bid & 63, part = bid >> 6;
    if (tid < 8) {
        int grow = rowgrp * 8 + tid;
        sidx[tid] = (grow >= 256) ? r_idx[grow - 256] : l_idx[grow];
    }
    __syncthreads();
    for (int e = tid; e < 8 * 300; e += 256) {
        int rr = e / 300, t = e - rr * 300;
        xs[e] = emb[(long)sidx[rr] * 300 + t];
    }
    __syncthreads();
    int col = part * 256 + tid;
    float bias = b_ioux[col] + b_iouh[col];
    float acc[8];
#pragma unroll
    for (int r = 0; r < 8; r++) acc[r] = bias;
#pragma unroll 6
    for (int t = 0; t < 300; t++) {
        float w = g_WxT[t * 768 + col];
#pragma unroll
        for (int r = 0; r < 8; r++) acc[r] = fmaf(w, xs[r * 300 + t], acc[r]);
    }
#pragma unroll
    for (int r = 0; r < 8; r++) g_iou[(rowgrp * 8 + r) * 768 + col] = acc[r];
}

__device__ void st_leafgate(int bid, int tid) {
    for (int row = bid; row < 512; row += NBLK) {
        int side = row >> 8, leaf = row & 255;
        const float* base = &g_iou[row * 768];
        float iv = sigm(base[tid]);
        float ov = sigm(base[256 + tid]);
        float uv = tanhf(base[512 + tid]);
        float c = iv * uv;
        float h = ov * tanhf(c);
        g_c[side][leaf * 256 + tid] = c;
        g_mat[side][leaf * 256 + tid] = h;
    }
}

// ---- vectorized accum inner core (float4 LDS over 4 e-steps; order-preserving) ----
template <int RT>
__device__ __forceinline__ void accum_core(const float* smf, int tid, int e0, int eNa,
                                           float* a0, float* a1, float* a2, float* a3, float* a4) {
#pragma unroll 2
    for (int ee = 0; ee < eNa; ee += 4) {
        float4 w0 = g_Wpack[(e0 + ee) * 256 + tid];
        float4 w1 = g_Wpack[(e0 + ee + 1) * 256 + tid];
        float4 w2 = g_Wpack[(e0 + ee + 2) * 256 + tid];
        float4 w3 = g_Wpack[(e0 + ee + 3) * 256 + tid];
#pragma unroll
        for (int r = 0; r < RT; r++) {
            float4 h0v = *(const float4*)&smf[r * 2 * eNa + ee];
            float4 h1v = *(const float4*)&smf[r * 2 * eNa + eNa + ee];
            float hv;
            hv = h0v.x + h1v.x;
            a0[r] = fmaf(w0.x, hv, a0[r]); a1[r] = fmaf(w0.y, hv, a1[r]); a2[r] = fmaf(w0.z, hv, a2[r]);
            a3[r] = fmaf(w0.w, h0v.x, a3[r]); a4[r] = fmaf(w0.w, h1v.x, a4[r]);
            hv = h0v.y + h1v.y;
            a0[r] = fmaf(w1.x, hv, a0[r]); a1[r] = fmaf(w1.y, hv, a1[r]); a2[r] = fmaf(w1.z, hv, a2[r]);
            a3[r] = fmaf(w1.w, h0v.y, a3[r]); a4[r] = fmaf(w1.w, h1v.y, a4[r]);
            hv = h0v.z + h1v.z;
            a0[r] = fmaf(w2.x, hv, a0[r]); a1[r] = fmaf(w2.y, hv, a1[r]); a2[r] = fmaf(w2.z, hv, a2[r]);
            a3[r] = fmaf(w2.w, h0v.z, a3[r]); a4[r] = fmaf(w2.w, h1v.z, a4[r]);
            hv = h0v.w + h1v.w;
            a0[r] = fmaf(w3.x, hv, a0[r]); a1[r] = fmaf(w3.y, hv, a1[r]); a2[r] = fmaf(w3.z, hv, a2[r]);
            a3[r] = fmaf(w3.w, h0v.w, a3[r]); a4[r] = fmaf(w3.w, h1v.w, a4[r]);
        }
    }
}

// vectorized partial reduce into smem buf[0..1279] (R11-proven)
__device__ __forceinline__ void reduce_parts(float* buf, int tid, int g, int node, int ES) {
    float4 A0 = make_float4(0, 0, 0, 0), A1 = make_float4(0, 0, 0, 0);
#pragma unroll 4
    for (int s = 0; s < ES; s++) {
        const float4* t4 = (const float4*)&g_treePart[g][(node * ES + s) * 1280];
        float4 v = __ldcg(t4 + tid);
        A0.x += v.x; A0.y += v.y; A0.z += v.z; A0.w += v.w;
        if (tid < 64) {
            v = __ldcg(t4 + 256 + tid);
            A1.x += v.x; A1.y += v.y; A1.z += v.z; A1.w += v.w;
        }
    }
    float4* b4 = (float4*)buf;
    b4[tid] = A0;
    if (tid < 64) b4[256 + tid] = A1;
    __syncthreads();
}

// ---------- NO-ATTN fused accum + counter + gate (one stage per level) ----------
template <int RT>
__device__ void st_accumFuse(int gb, int tid, float* smf, int g, int lev,
                             const float* __restrict__ bi, const float* __restrict__ bf) {
    int k = 256 >> lev, ES = c_ES0[lev];
    int eNa = 256 / ES, tgc = k / RT;
    if (gb >= tgc * ES) return;
    int tg = gb / ES, es_ = gb - tg * ES, e0 = es_ * eNa;
    int offp = c_off[lev - 1], offc = c_off[lev];
    const float* hsrc = g_mat[g];
    int cnt = RT * 2 * eNa;
    for (int t = tid; t < cnt; t += 256) {
        int r = t / (2 * eNa), rem = t - r * 2 * eNa;
        int cc = rem / eNa, e = rem - cc * eNa;
        smf[t] = hsrc[(offp + 2 * (tg * RT + r) + cc) * 256 + e0 + e];
    }
    __syncthreads();
    float a0[RT], a1[RT], a2[RT], a3[RT], a4[RT];
#pragma unroll
    for (int r = 0; r < RT; r++) { a0[r] = a1[r] = a2[r] = a3[r] = a4[r] = 0.f; }
    accum_core<RT>(smf, tid, e0, eNa, a0, a1, a2, a3, a4);
#pragma unroll
    for (int r = 0; r < RT; r++) {
        float* b = &g_treePart[g][((tg * RT + r) * ES + es_) * 1280];
        b[tid] = a0[r]; b[256 + tid] = a1[r]; b[512 + tid] = a2[r];
        b[768 + tid] = a3[r]; b[1024 + tid] = a4[r];
    }
    __threadfence();
    __shared__ int fin;
    if (tid == 0) fin = (atomicAdd(&g_cnt0[g][lev - 1][tg], 1) == ES - 1);
    __syncthreads();
    if (!fin) return;
    for (int r = 0; r < RT; r++) {
        int node = tg * RT + r;
        reduce_parts(smf, tid, g, node, ES);
        float iv = sigm(smf[tid] + bi[tid]);
        float ov = sigm(smf[256 + tid] + bi[256 + tid]);
        float uv = tanhf(smf[512 + tid] + bi[512 + tid]);
        float f0 = sigm(smf[768 + tid] + bf[tid]);
        float f1 = sigm(smf[1024 + tid] + bf[tid]);
        const float* csrc = &g_c[g][(offp + 2 * node) * 256];
        float c = iv * uv + f0 * csrc[tid] + f1 * csrc[256 + tid];
        float h = ov * tanhf(c);
        g_c[g][(offc + node) * 256 + tid] = c;
        g_mat[g][(offc + node) * 256 + tid] = h;
        __syncthreads();
    }
}

__device__ void accumFuse_d(int gb, int tid, float* smf, int g, int lev,
                            const float* bi, const float* bf) {
    int rt = c_RT0[lev];
    if (rt == 4) st_accumFuse<4>(gb, tid, smf, g, lev, bi, bf);
    else if (rt == 2) st_accumFuse<2>(gb, tid, smf, g, lev, bi, bf);
    else st_accumFuse<1>(gb, tid, smf, g, lev, bi, bf);
}

// ---------- attended split-K accum (vectorized core, structure unchanged) ----------
template <int RT>
__device__ void st_accumG(int gb, int tid, float* smf, int g, int lev) {
    int k = 256 >> lev, ES = c_ES[lev];
    int tg_cnt = k / RT;
    if (gb >= tg_cnt * ES) return;
    int tg = gb / ES, es_ = gb - tg * ES;
    int eNa = 256 / ES, e0 = es_ * eNa;
    int offp = c_off[lev - 1];
    const float* hsrc = g_hA[g];
    int cnt = RT * 2 * eNa;
    for (int t = tid; t < cnt; t += 256) {
        int r = t / (2 * eNa), rem = t - r * 2 * eNa;
        int cc = rem / eNa, e = rem - cc * eNa;
        smf[t] = hsrc[(offp + 2 * (tg * RT + r) + cc) * 256 + e0 + e];
    }
    __syncthreads();
    float a0[RT], a1[RT], a2[RT], a3[RT], a4[RT];
#pragma unroll
    for (int r = 0; r < RT; r++) { a0[r] = a1[r] = a2[r] = a3[r] = a4[r] = 0.f; }
    accum_core<RT>(smf, tid, e0, eNa, a0, a1, a2, a3, a4);
#pragma unroll
    for (int r = 0; r < RT; r++) {
        float* b = &g_treePart[g][((tg * RT + r) * ES + es_) * 1280];
        b[tid] = a0[r]; b[256 + tid] = a1[r]; b[512 + tid] = a2[r];
        b[768 + tid] = a3[r]; b[1024 + tid] = a4[r];
    }
}

__device__ void accumG_d(int gb, int tid, float* smf, int g, int lev) {
    int rt = c_RT[lev];
    if (rt == 8) st_accumG<8>(gb, tid, smf, g, lev);
    else if (rt == 4) st_accumG<4>(gb, tid, smf, g, lev);
    else if (rt == 2) st_accumG<2>(gb, tid, smf, g, lev);
    else st_accumG<1>(gb, tid, smf, g, lev);
}

// ---------- attended gate (block per node); dohp => also hp = W1 @ h ----------
__device__ void st_gateG(int gb, int tid, float* smf, int g, int lev, int dohp,
                         const float* __restrict__ bi, const float* __restrict__ bf) {
    int k = 256 >> lev;
    if (gb >= k) return;
    int node = gb;
    int offp = c_off[lev - 1], offc = c_off[lev];
    reduce_parts(smf, tid, g, node, c_ES[lev]);
    float iv = sigm(smf[tid] + bi[tid]);
    float ov = sigm(smf[256 + tid] + bi[256 + tid]);
    float uv = tanhf(smf[512 + tid] + bi[512 + tid]);
    float f0 = sigm(smf[768 + tid] + bf[tid]);
    float f1 = sigm(smf[1024 + tid] + bf[tid]);
    const float* csrc = (lev == 1) ? &g_c[1 - g][(2 * node) * 256]
                                   : &g_cA[g][(offp + 2 * node) * 256];
    float c = iv * uv + f0 * csrc[tid] + f1 * csrc[256 + tid];
    float h = ov * tanhf(c);
    g_cA[g][(offc + node) * 256 + tid] = c;
    g_hPre[g][(offc + node) * 256 + tid] = h;
    if (dohp) {
        float* hsm = smf + 1280; float* hpP = smf + 1536;
        hsm[tid] = h;
        __syncthreads();
        int w = tid >> 5, lane = tid & 31;
        float a[8] = {0, 0, 0, 0, 0, 0, 0, 0};
        for (int ei = 0; ei < 32; ei++) {
            int e = w * 32 + ei; float hv = hsm[e];
#pragma unroll
            for (int c2 = 0; c2 < 8; c2++) a[c2] = fmaf(g_W1T[e * 256 + c2 * 32 + lane], hv, a[c2]);
        }
#pragma unroll
        for (int c2 = 0; c2 < 8; c2++) hpP[w * 256 + c2 * 32 + lane] = a[c2];
        __syncthreads();
        float s = 0;
#pragma unroll
        for (int w2 = 0; w2 < 8; w2++) s += hpP[w2 * 256 + tid];
        g_hp[g][node * 256 + tid] = s;
    }
}

// ---------- proj -> pbT + colsum ----------
__device__ void st_projG(int gb, int tid, float* smf, int g, const float* __restrict__ ba) {
    if (gb < 128) {
        int mb = gb * 4;
        float* ms = smf;
#pragma unroll
        for (int r = 0; r < 4; r++) {
            int m = min(mb + r, 510);
            ms[r * 256 + tid] = g_mat[g][m * 256 + tid];
        }
        __syncthreads();
        float b0 = ba[tid]; float a0 = b0, a1 = b0, a2 = b0, a3 = b0;
#pragma unroll 8
        for (int e = 0; e < 256; e++) {
            float w = g_W2T[e * 256 + tid];
            a0 = fmaf(w, ms[e], a0);       a1 = fmaf(w, ms[256 + e], a1);
            a2 = fmaf(w, ms[512 + e], a2); a3 = fmaf(w, ms[768 + e], a3);
        }
        *(float4*)&g_pbT[g][tid * 512 + mb] = make_float4(a0, a1, a2, a3);
    } else if (gb < 132) {
        int qc = gb - 128;
        int d = tid & 63, rs = tid >> 6, dim = qc * 64 + d;
        float a = 0;
        for (int m = rs; m < 511; m += 4) a += g_mat[g][m * 256 + dim];
        float* red = smf;
        red[rs * 64 + d] = a;
        __syncthreads();
        if (rs == 0) g_colsum[g][dim] = red[d] + red[64 + d] + red[128 + d] + red[192 + d];
    }
}

// ---------- fused attend (lev 0..3): hp + scores + softmax + combine ----------
template <int R>
__device__ void st_attendF(int gb, int tid, float* smf, int g, int lev,
                           const float* __restrict__ Wa) {
    int rows = 256 >> lev;
    int rg = rows / R;
    if (gb >= rg) return;
    int nb = gb * R;
    int roff = c_off[lev];
    float* hsm = smf;
    float* wa  = hsm + R * 256;
    float* hpP = wa + 256;
    float* es  = hpP + 8 * R * 256;
    float* red = es + R * 512;
    float4* sp = (float4*)(red + 16);
    const float* hsrc = lev ? g_hPre[g] : g_mat[1 - g];
#pragma unroll
    for (int r = 0; r < R; r++) hsm[r * 256 + tid] = hsrc[(roff + nb + r) * 256 + tid];
    wa[tid] = Wa[tid];
    __syncthreads();
    int w = tid >> 5, lane = tid & 31;
    {
        float acc[R][8];
#pragma unroll
        for (int r = 0; r < R; r++)
#pragma unroll
            for (int c = 0; c < 8; c++) acc[r][c] = 0.f;
        for (int ei = 0; ei < 32; ei++) {
            int e = w * 32 + ei;
#pragma unroll
            for (int c = 0; c < 8; c++) {
                float w1 = g_W1T[e * 256 + c * 32 + lane];
#pragma unroll
                for (int r = 0; r < R; r++) acc[r][c] = fmaf(w1, hsm[r * 256 + e], acc[r][c]);
            }
        }
#pragma unroll
        for (int r = 0; r < R; r++)
#pragma unroll
            for (int c = 0; c < 8; c++) hpP[w * R * 256 + r * 256 + c * 32 + lane] = acc[r][c];
    }
    __syncthreads();
    float hpr[R];
#pragma unroll
    for (int r = 0; r < R; r++) {
        float s = 0;
#pragma unroll
        for (int w2 = 0; w2 < 8; w2++) s += hpP[w2 * R * 256 + r * 256 + tid];
        hpr[r] = s;
    }
    __syncthreads();
#pragma unroll
    for (int r = 0; r < R; r++) hpP[r * 256 + tid] = hpr[r];
    __syncthreads();
    float sa[R][2];
#pragma unroll
    for (int r = 0; r < R; r++) { sa[r][0] = 0.f; sa[r][1] = 0.f; }
    const float* pbb = g_pbT[g];
#pragma unroll 4
    for (int d = 0; d < 256; d++) {
        float pb0 = pbb[d * 512 + tid];
        float pb1 = pbb[d * 512 + 256 + tid];
        float wv = wa[d];
#pragma unroll
        for (int r = 0; r < R; r++) {
            float hv = hpP[r * 256 + d];
            sa[r][0] = fmaf(wv, tfast(hv + pb0), sa[r][0]);
            sa[r][1] = fmaf(wv, tfast(hv + pb1), sa[r][1]);
        }
    }
#pragma unroll
    for (int r = 0; r < R; r++) {
        es[r * 512 + tid] = __expf(sa[r][0]);
        es[r * 512 + 256 + tid] = (tid == 255) ? 0.f : __expf(sa[r][1]);
    }
    __syncthreads();
    float inv[R];
#pragma unroll
    for (int r = 0; r < R; r++)
        inv[r] = 1.0f / blksum(es[r * 512 + tid] + es[r * 512 + 256 + tid], red, tid);
    int q = tid & 63, st2 = tid >> 6;
    const float4* m4 = (const float4*)g_mat[g];
    float4 a2[R];
#pragma unroll
    for (int r = 0; r < R; r++) a2[r] = make_float4(0, 0, 0, 0);
#pragma unroll 8
    for (int m = st2; m < 511; m += 4) {
        float4 mv = m4[m * 64 + q];
#pragma unroll
        for (int r = 0; r < R; r++) {
            float e = es[r * 512 + m];
            a2[r].x = fmaf(e, mv.x, a2[r].x); a2[r].y = fmaf(e, mv.y, a2[r].y);
            a2[r].z = fmaf(e, mv.z, a2[r].z); a2[r].w = fmaf(e, mv.w, a2[r].w);
        }
    }
#pragma unroll
    for (int r = 0; r < R; r++) sp[(st2 * R + r) * 64 + q] = a2[r];
    __syncthreads();
    if (st2 == 0) {
        const float* cs = g_colsum[g];
#pragma unroll
        for (int r = 0; r < R; r++) {
            float4 t = sp[r * 64 + q];
            float4 b1 = sp[(R + r) * 64 + q], b2 = sp[(2 * R + r) * 64 + q], b3 = sp[(3 * R + r) * 64 + q];
            t.x += b1.x + b2.x + b3.x; t.y += b1.y + b2.y + b3.y;
            t.z += b1.z + b2.z + b3.z; t.w += b1.w + b2.w + b3.w;
            float* o = &g_hA[g][(roff + nb + r) * 256 + 4 * q];
            o[0] = cs[4 * q + 0] - t.x * inv[r] + hsm[r * 256 + 4 * q + 0];
            o[1] = cs[4 * q + 1] - t.y * inv[r] + hsm[r * 256 + 4 * q + 1];
            o[2] = cs[4 * q + 2] - t.z * inv[r] + hsm[r * 256 + 4 * q + 2];
            o[3] = cs[4 * q + 3] - t.w * inv[r] + hsm[r * 256 + 4 * q + 3];
        }
    }
}

// ---------- deep attend (lev 4..8): block per row, hp precomputed in gate ----------
__device__ void st_attendD(int gb, int tid, float* smf, int g, int lev,
                           const float* __restrict__ Wa) {
    int k = 256 >> lev;
    if (gb >= k) return;
    int n = gb, grow = c_off[lev] + n;
    float* hp = smf; float* wa = hp + 256; float* es = wa + 256;
    float* red = es + 512; float* hr = red + 16;
    float4* sp = (float4*)(hr + 256);
    hp[tid] = __ldcg(&g_hp[g][n * 256 + tid]);
    wa[tid] = Wa[tid];
    hr[tid] = g_hPre[g][grow * 256 + tid];
    __syncthreads();
    float s0 = 0.f, s1 = 0.f;
    const float* pbb = g_pbT[g];
#pragma unroll 4
    for (int d = 0; d < 256; d++) {
        float pb0 = pbb[d * 512 + tid];
        float pb1 = pbb[d * 512 + 256 + tid];
        float wv = wa[d], hv = hp[d];
        s0 = fmaf(wv, tfast(hv + pb0), s0);
        s1 = fmaf(wv, tfast(hv + pb1), s1);
    }
    es[tid] = __expf(s0);
    es[256 + tid] = (tid == 255) ? 0.f : __expf(s1);
    __syncthreads();
    float inv = 1.0f / blksum(es[tid] + es[256 + tid], red, tid);
    int q = tid & 63, st2 = tid >> 6;
    const float4* m4 = (const float4*)g_mat[g];
    float4 a = make_float4(0, 0, 0, 0);
#pragma unroll 8
    for (int m = st2; m < 511; m += 4) {
        float4 mv = m4[m * 64 + q]; float e = es[m];
        a.x = fmaf(e, mv.x, a.x); a.y = fmaf(e, mv.y, a.y);
        a.z = fmaf(e, mv.z, a.z); a.w = fmaf(e, mv.w, a.w);
    }
    sp[st2 * 64 + q] = a;
    __syncthreads();
    if (st2 == 0) {
        float4 t = sp[q], b1 = sp[64 + q], b2 = sp[128 + q], b3 = sp[192 + q];
        t.x += b1.x + b2.x + b3.x; t.y += b1.y + b2.y + b3.y;
        t.z += b1.z + b2.z + b3.z; t.w += b1.w + b2.w + b3.w;
        const float* cs = g_colsum[g];
        float* o = &g_hA[g][grow * 256 + 4 * q];
        o[0] = cs[4 * q + 0] - t.x * inv + hr[4 * q + 0];
        o[1] = cs[4 * q + 1] - t.y * inv + hr[4 * q + 1];
        o[2] = cs[4 * q + 2] - t.z * inv + hr[4 * q + 2];
        o[3] = cs[4 * q + 3] - t.w * inv + hr[4 * q + 3];
    }
}

__device__ void st_final(int tid, float* smf,
                         const float* __restrict__ W_wh, const float* __restrict__ b_wh,
                         const float* __restrict__ W_wp, const float* __restrict__ b_wp,
                         float* __restrict__ out) {
    float* v = smf; float* hid = smf + 512;
    float lh = tanhf(g_mat[0][510 * 256 + tid] + g_hA[1][510 * 256 + tid]);
    float rh = tanhf(g_hA[0][510 * 256 + tid] + g_mat[1][510 * 256 + tid]);
    v[tid] = lh * rh;
    v[256 + tid] = fabsf(lh - rh);
    __syncthreads();
    if (tid < 128) {
        float a = b_wh[tid];
        const float4* W4 = (const float4*)&W_wh[tid * 512];
        const float4* v4 = (const float4*)v;
#pragma unroll 8
        for (int e = 0; e < 128; e++) {
            float4 w = W4[e], x = v4[e];
            a = fmaf(w.x, x.x, fmaf(w.y, x.y, fmaf(w.z, x.z, fmaf(w.w, x.w, a))));
        }
        hid[tid] = sigm(a);
    }
    __syncthreads();
    if (tid < 32) {
        float z[5];
#pragma unroll
        for (int c = 0; c < 5; c++) {
            float a = 0.f;
            for (int e = tid; e < 128; e += 32) a = fmaf(W_wp[c * 128 + e], hid[e], a);
#pragma unroll
            for (int o = 16; o; o >>= 1) a += __shfl_xor_sync(~0u, a, o);
            z[c] = a + b_wp[c];
        }
        if (tid == 0) {
            float mx = z[0];
#pragma unroll
            for (int c = 1; c < 5; c++) mx = fmaxf(mx, z[c]);
            float s = 0.f;
#pragma unroll
            for (int c = 0; c < 5; c++) s += expf(z[c] - mx);
            float ls = logf(s);
#pragma unroll
            for (int c = 0; c < 5; c++) out[c] = z[c] - mx - ls;
        }
    }
}

// ================= persistent mega kernel =================
__global__ void __launch_bounds__(256, 2)
mega_kernel(const int* l_idx, const int* r_idx, const float* emb,
            const float* W_ioux, const float* b_ioux,
            const float* W_iouh, const float* b_iouh,
            const float* W_fh, const float* b_fh,
            const float* Wa, const float* b_attnh,
            const float* W_wh, const float* b_wh,
            const float* W_wp, const float* b_wp,
            const float* W_attnh, float* out) {
    __shared__ __align__(16) float smf[11600];
    int bid = blockIdx.x, tid = threadIdx.x;
    int g = bid >= GBLK, gb = bid - g * GBLK;

    st_prep(bid, tid, W_ioux, W_iouh, W_fh, W_attnh);               gbarG(0);
    st_leafgemm(bid, tid, smf, l_idx, r_idx, emb, b_ioux, b_iouh);  gbarG(1);
    st_leafgate(bid, tid);                                          gbarG(2);

    int b = 0;
    // no-attn tree: ONE fused stage per level
    for (int lev = 1; lev <= 8; lev++) {
        accumFuse_d(gb, tid, smf, g, lev, b_iouh, b_fh);            gbarL(g, b++);
    }
    st_projG(gb, tid, smf, g, b_attnh);                             gbarL(g, b++);
    st_attendF<2>(gb, tid, smf, g, 0, Wa);                          gbarL(g, b++);
    for (int lev = 1; lev <= 3; lev++) {
        accumG_d(gb, tid, smf, g, lev);                             gbarL(g, b++);
        st_gateG(gb, tid, smf, g, lev, 0, b_iouh, b_fh);            gbarL(g, b++);
        st_attendF<1>(gb, tid, smf, g, lev, Wa);                    gbarL(g, b++);
    }
    for (int lev = 4; lev <= 8; lev++) {
        accumG_d(gb, tid, smf, g, lev);                             gbarL(g, b++);
        st_gateG(gb, tid, smf, g, lev, 1, b_iouh, b_fh);            gbarL(g, b++);
        st_attendD(gb, tid, smf, g, lev, Wa);                       gbarL(g, b++);
    }
    gbarG(3);
    if (bid == 0) st_final(tid, smf, W_wh, b_wh, W_wp, b_wp, out);
}

// ================= host =================
extern "C" void kernel_launch(void* const* d_in, const int* in_sizes, int n_in,
                              void* d_out, int out_size) {
    const int*   l_idx   = (const int*)d_in[0];
    const int*   r_idx   = (const int*)d_in[1];
    const float* emb     = (const float*)d_in[2];
    const float* W_ioux  = (const float*)d_in[3];
    const float* b_ioux  = (const float*)d_in[4];
    const float* W_iouh  = (const float*)d_in[5];
    const float* b_iouh  = (const float*)d_in[6];
    const float* W_fh    = (const float*)d_in[9];
    const float* b_fh    = (const float*)d_in[10];
    const float* Wa      = (const float*)d_in[11];
    const float* W_attnh = (const float*)d_in[12];
    const float* b_attnh = (const float*)d_in[13];
    const float* W_wh    = (const float*)d_in[14];
    const float* b_wh    = (const float*)d_in[15];
    const float* W_wp    = (const float*)d_in[16];
    const float* b_wp    = (const float*)d_in[17];
    float* out = (float*)d_out;

    reset_kernel<<<1, 256>>>();
    mega_kernel<<<NBLK, 256>>>(l_idx, r_idx, emb,
                               W_ioux, b_ioux, W_iouh, b_iouh, W_fh, b_fh,
                               Wa, b_attnh, W_wh, b_wh, W_wp, b_wp,
                               W_attnh, out);
}